// round 14
// baseline (speedup 1.0000x reference)
#include <cuda_runtime.h>
#include <cuda_fp16.h>
#include <cstdint>

namespace {
constexpr int Cc = 64, Tt = 64, Vv = 325, TPB = 192;
constexpr int NCHUNK = 21;       // k16 chunks (21*16 = 336 >= 325)
constexpr int XBLK  = 18432;     // one 128-v block: X[128][72] fp16 (also hosts UT)
constexpr int GSTR  = 48;        // G row stride (16B-aligned; 12-word stride = conflict-free)
constexpr int GCH   = 384 * GSTR;            // 18432 per chunk buffer
constexpr int SM_X  = 0;         // 3 blocks = 55296 ; reused as Os[32][396] f32 (50688)
constexpr int SM_W  = 55296;     // W1[32][72], W0'[32][72] fp16, stride 144B: 2 x 4608
constexpr int SM_G  = 64512;     // 2 bufs x 18432
constexpr int SM_BIAS = 101376;
constexpr int SM_TOTAL = 101632; // x2 CTAs = 203 KB <= 228 KB
}

// Pre-converted gso, fp16: per chunk [336 rows x 16 k] at 48B row stride
__device__ __align__(16) unsigned char g_gso_f16[NCHUNK * GCH];   // ~387 KB

__device__ __forceinline__ uint32_t smem_u32(const void* p) {
    uint32_t a;
    asm("{ .reg .u64 tmp; cvta.to.shared.u64 tmp, %1; cvt.u32.u64 %0, tmp; }"
        : "=r"(a) : "l"(p));
    return a;
}
__device__ __forceinline__ void cpasync16(uint32_t dst, const void* src) {
    asm volatile("cp.async.cg.shared.global [%0], [%1], 16;"
                 :: "r"(dst), "l"(src) : "memory");
}
// copy one chunk: 1008 x 16B = 16128 B (rows 0-335; rows >=336 stale = discarded v)
__device__ __forceinline__ void copy_chunk(uint32_t dst, const unsigned char* src,
                                           int tid) {
    #pragma unroll
    for (int u = tid; u < 1008; u += TPB)
        cpasync16(dst + (uint32_t)u * 16, src + (uint32_t)u * 16);
}

#define LDSM4(r0, r1, r2, r3, addr)                                            \
    asm volatile("ldmatrix.sync.aligned.m8n8.x4.shared.b16 {%0,%1,%2,%3}, [%4];" \
                 : "=r"(r0), "=r"(r1), "=r"(r2), "=r"(r3) : "r"(addr))

#define MMA(d, a0, a1, a2, a3, b0, b1)                                         \
    asm volatile("mma.sync.aligned.m16n8k16.row.col.f32.f16.f16.f32 "          \
                 "{%0,%1,%2,%3},{%4,%5,%6,%7},{%8,%9},{%0,%1,%2,%3};"          \
                 : "+f"((d)[0]), "+f"((d)[1]), "+f"((d)[2]), "+f"((d)[3])      \
                 : "r"(a0), "r"(a1), "r"(a2), "r"(a3), "r"(b0), "r"(b1))

// ---------------- prepass: gso f32 -> fp16 k16-chunk images (48B rows) ------------
__global__ void prep_gso(const float* __restrict__ gso)
{
    int idx = blockIdx.x * blockDim.x + threadIdx.x;     // NCHUNK*336*16
    if (idx >= NCHUNK * 336 * 16) return;
    int kk = idx / (336 * 16);
    int r  = (idx / 16) % 336;
    int c  = idx & 15;
    int kg = kk * 16 + c;
    float val = (r < Vv && kg < Vv) ? gso[(size_t)r * Vv + kg] : 0.0f;
    *(__half*)(g_gso_f16 + (size_t)kk * GCH + r * GSTR + c * 2) = __float2half_rn(val);
}

// ---------------- main: 2 CTAs per (b,t), each 32 N-channels; 6 warps x 64 M-rows --
__global__ void __launch_bounds__(TPB, 2)
gconv_hmma(const float* __restrict__ x, const float* __restrict__ gso,
           const float* __restrict__ w, const float* __restrict__ bias,
           float* __restrict__ out)
{
    extern __shared__ unsigned char smem[];
    const uint32_t sb = smem_u32(smem);
    const int tid = threadIdx.x, wid = tid >> 5, lid = tid & 31;
    const int nh = blockIdx.x & 1;           // N-half: channels [nh*32, nh*32+32)
    const int bt = blockIdx.x >> 1, b = bt >> 6, t = bt & 63;

    // ---- kick off chunk-0 gso copy immediately (overlaps X staging + phase 1) ----
    copy_chunk(sb + SM_G, g_gso_f16, tid);
    asm volatile("cp.async.commit_group;" ::: "memory");

    // ---- bias -> smem (all 64; indexed with nh offset later) ----
    if (tid < Cc) ((float*)(smem + SM_BIAS))[tid] = bias[tid];

    // ---- weight halves as B-operands [c_local][i] (stride 144B), single fp16 ----
    // out = xp @ W[0] + (gso@xp) @ W[1] + bias + x
    for (int e = tid; e < 32 * Cc; e += TPB) {
        int i = e >> 5, cl = e & 31, cg = nh * 32 + cl;
        float w1 = w[Cc * Cc + i * Cc + cg];             // gso path (U = X@W1)
        float w0 = w[i * Cc + cg] + (i == cg ? 1.0f : 0.0f);  // direct + residual
        uint32_t off = (uint32_t)(cl * 144 + i * 2);
        *(__half*)(smem + SM_W + off)        = __float2half_rn(w1);
        *(__half*)(smem + SM_W + 4608 + off) = __float2half_rn(w0);
    }

    // ---- X as A-operand [v][i] (stride 144B), single fp16, full 64 channels ----
    const float* xb = x + ((size_t)(b * Cc) * Tt + t) * Vv;
    #pragma unroll
    for (int ii = 0; ii < 11; ii++) {
        int i = wid + 6 * ii;
        if (i < Cc) {
            const float* xr = xb + (size_t)i * Tt * Vv;
            for (int v = lid; v < 384; v += 32) {
                float val = (v < Vv) ? xr[v] : 0.0f;
                uint32_t off = (uint32_t)((v >> 7) * XBLK + (v & 127) * 144 + i * 2);
                *(__half*)(smem + SM_X + off) = __float2half_rn(val);
            }
        }
    }
    __syncthreads();

    // warp owns M-rows [wid*64, wid*64+64): 4 m16 subtiles
    #define XA(s) (sb + SM_X + (wid >> 1) * XBLK + \
                   ((wid & 1) * 64 + (s) * 16 + (lid & 15)) * 144 + (lid >> 4) * 16)

    // ================= phase 1a: U = X@W1 (uacc only; keeps reg peak low) ==========
    float uacc[4][4][4] = {};
    #pragma unroll
    for (int k = 0; k < 4; k++) {
        uint32_t a[4][4];
        #pragma unroll
        for (int s = 0; s < 4; s++)
            LDSM4(a[s][0], a[s][1], a[s][2], a[s][3], XA(s) + k * 32);
        uint32_t h[2][4];
        #pragma unroll
        for (int np = 0; np < 2; np++)
            LDSM4(h[np][0], h[np][1], h[np][2], h[np][3],
                  sb + SM_W + (np * 16 + (lid & 15)) * 144 + (lid >> 4) * 16 + k * 32);
        #pragma unroll
        for (int s = 0; s < 4; s++)
            #pragma unroll
            for (int np = 0; np < 2; np++) {
                MMA(uacc[s][np * 2],     a[s][0], a[s][1], a[s][2], a[s][3],
                    h[np][0], h[np][2]);
                MMA(uacc[s][np * 2 + 1], a[s][0], a[s][1], a[s][2], a[s][3],
                    h[np][1], h[np][3]);
            }
    }

    // ================= phase 1b: oacc = bias + X@W0' ================================
    const float* bsm = (const float*)(smem + SM_BIAS);
    float oacc[4][4][4];
    #pragma unroll
    for (int s = 0; s < 4; s++)
        #pragma unroll
        for (int nt = 0; nt < 4; nt++)
            #pragma unroll
            for (int r = 0; r < 4; r++)
                oacc[s][nt][r] = bsm[nh * 32 + nt * 8 + (lid & 3) * 2 + (r & 1)];
    #pragma unroll
    for (int k = 0; k < 4; k++) {
        uint32_t a[4][4];
        #pragma unroll
        for (int s = 0; s < 4; s++)
            LDSM4(a[s][0], a[s][1], a[s][2], a[s][3], XA(s) + k * 32);
        uint32_t h[2][4];
        #pragma unroll
        for (int np = 0; np < 2; np++)
            LDSM4(h[np][0], h[np][1], h[np][2], h[np][3],
                  sb + SM_W + 4608 + (np * 16 + (lid & 15)) * 144 + (lid >> 4) * 16 + k * 32);
        #pragma unroll
        for (int s = 0; s < 4; s++)
            #pragma unroll
            for (int np = 0; np < 2; np++) {
                MMA(oacc[s][np * 2],     a[s][0], a[s][1], a[s][2], a[s][3],
                    h[np][0], h[np][2]);
                MMA(oacc[s][np * 2 + 1], a[s][0], a[s][1], a[s][2], a[s][3],
                    h[np][1], h[np][3]);
            }
    }
    __syncthreads();   // all warps done reading X

    // write UT: [c_local][k'] single fp16, stride 272B per 128-block (overlays X)
    #pragma unroll
    for (int s = 0; s < 4; s++)
        #pragma unroll
        for (int nt = 0; nt < 4; nt++)
            #pragma unroll
            for (int r = 0; r < 4; r++) {
                int cl = nt * 8 + (lid & 3) * 2 + (r & 1);
                int kp = wid * 64 + s * 16 + (lid >> 2) + ((r >> 1) << 3);
                uint32_t off = (uint32_t)((kp >> 7) * XBLK + cl * 272 + (kp & 127) * 2);
                *(__half*)(smem + SM_X + off) = __float2half_rn(uacc[s][nt][r]);
            }

    asm volatile("cp.async.wait_group 0;" ::: "memory");
    __syncthreads();

    // ================= phase 2: oacc += G @ U, k16 chunks, pipelined =================
    for (int kk = 0; kk < NCHUNK; kk++) {
        if (kk < NCHUNK - 1) {
            copy_chunk(sb + SM_G + ((kk + 1) & 1) * GCH,
                       g_gso_f16 + (size_t)(kk + 1) * GCH, tid);
            asm volatile("cp.async.commit_group;" ::: "memory");
        }

        const uint32_t gb = sb + SM_G + (kk & 1) * GCH;
        const uint32_t ub = sb + SM_X + (kk >> 3) * XBLK + (kk & 7) * 32;

        uint32_t uf[2][4];
        #pragma unroll
        for (int np = 0; np < 2; np++)
            LDSM4(uf[np][0], uf[np][1], uf[np][2], uf[np][3],
                  ub + (np * 16 + (lid & 15)) * 272 + (lid >> 4) * 16);

        #pragma unroll
        for (int s = 0; s < 4; s++) {
            uint32_t a0, a1, a2, a3;
            LDSM4(a0, a1, a2, a3,
                  gb + (wid * 64 + s * 16 + (lid & 15)) * GSTR + (lid >> 4) * 16);
            #pragma unroll
            for (int np = 0; np < 2; np++) {
                MMA(oacc[s][np * 2],     a0, a1, a2, a3, uf[np][0], uf[np][2]);
                MMA(oacc[s][np * 2 + 1], a0, a1, a2, a3, uf[np][1], uf[np][3]);
            }
        }

        if (kk < NCHUNK - 1) {
            asm volatile("cp.async.wait_group 0;" ::: "memory");
            __syncthreads();
        }
    }
    __syncthreads();

    // ================= epilogue: transpose via smem, coalesced [c][v] stores =========
    float* Os = (float*)(smem + SM_X);   // [32][396] f32, UT dead
    #pragma unroll
    for (int s = 0; s < 4; s++)
        #pragma unroll
        for (int nt = 0; nt < 4; nt++)
            #pragma unroll
            for (int r = 0; r < 4; r++) {
                int cl = nt * 8 + (lid & 3) * 2 + (r & 1);
                int v  = wid * 64 + s * 16 + (lid >> 2) + ((r >> 1) << 3);
                Os[cl * 396 + v] = oacc[s][nt][r];
            }
    __syncthreads();
    float* ob = out + ((size_t)(b * Cc) * Tt + t) * Vv;
    for (int cl = wid; cl < 32; cl += 6) {
        float* orow = ob + (size_t)(nh * 32 + cl) * Tt * Vv;
        for (int v = lid; v < Vv; v += 32)
            orow[v] = Os[cl * 396 + v];
    }
}

extern "C" void kernel_launch(void* const* d_in, const int* in_sizes, int n_in,
                              void* d_out, int out_size)
{
    const float* x      = (const float*)d_in[0];
    const float* gso    = (const float*)d_in[1];
    const float* weight = (const float*)d_in[2];
    const float* bias   = (const float*)d_in[3];
    float* out = (float*)d_out;

    prep_gso<<<(NCHUNK * 336 * 16 + 255) / 256, 256>>>(gso);

    cudaFuncSetAttribute(gconv_hmma,
                         cudaFuncAttributeMaxDynamicSharedMemorySize, SM_TOTAL);
    gconv_hmma<<<32 * 64 * 2, TPB, SM_TOTAL>>>(x, gso, weight, bias, out);
}

// round 15
// speedup vs baseline: 1.2471x; 1.2471x over previous
#include <cuda_runtime.h>
#include <cuda_fp16.h>
#include <cstdint>

namespace {
constexpr int Cc = 64, Tt = 64, Vv = 325, TPB = 384;
constexpr int NCHUNK = 6;        // k64 chunks, exact: 6*64 = 384
constexpr int XBLK  = 18432;     // one 128-v block: X[128][72] fp16 (also hosts UT)
constexpr int GSTR  = 144;       // G row stride (16B-aligned, conflict-free)
constexpr int GCH   = 384 * GSTR;            // 55296 per chunk buffer
constexpr int SM_X  = 0;         // 3 blocks = 55296 ; reused as Os[64][396] f32
constexpr int SM_W  = 55296;     // W1h, W0h each [64][72] fp16 = 9216 B
constexpr int SM_G  = 55296 + 2 * 9216;      // 73728: 2 bufs x 55296
constexpr int SM_BIAS = SM_G + 2 * GCH;      // 184320
constexpr int SM_TOTAL = SM_BIAS + 256;      // 184576 B
}

// Pre-converted gso, fp16: per chunk [336 rows x 64 k] at 144B row stride
__device__ __align__(16) unsigned char g_gso_f16[NCHUNK * GCH];   // ~324 KB

__device__ __forceinline__ uint32_t smem_u32(const void* p) {
    uint32_t a;
    asm("{ .reg .u64 tmp; cvta.to.shared.u64 tmp, %1; cvt.u32.u64 %0, tmp; }"
        : "=r"(a) : "l"(p));
    return a;
}
__device__ __forceinline__ void cpasync16(uint32_t dst, const void* src) {
    asm volatile("cp.async.cg.shared.global [%0], [%1], 16;"
                 :: "r"(dst), "l"(src) : "memory");
}
// copy one chunk: 3024 x 16B = 48384 B = rows 0-335 (contiguous row-major).
// Rows >=336 of the smem buffer are never written: they feed only v>=336
// outputs, which are discarded by the v<Vv store guard. k-columns >=325
// multiply U rows that are exactly zero, so their values are harmless.
__device__ __forceinline__ void copy_chunk(uint32_t dst, const unsigned char* src,
                                           int tid) {
    #pragma unroll
    for (int u = tid; u < 3024; u += TPB)
        cpasync16(dst + (uint32_t)u * 16, src + (uint32_t)u * 16);
}

#define LDSM4(r0, r1, r2, r3, addr)                                            \
    asm volatile("ldmatrix.sync.aligned.m8n8.x4.shared.b16 {%0,%1,%2,%3}, [%4];" \
                 : "=r"(r0), "=r"(r1), "=r"(r2), "=r"(r3) : "r"(addr))

#define MMA(d, a0, a1, a2, a3, b0, b1)                                         \
    asm volatile("mma.sync.aligned.m16n8k16.row.col.f32.f16.f16.f32 "          \
                 "{%0,%1,%2,%3},{%4,%5,%6,%7},{%8,%9},{%0,%1,%2,%3};"          \
                 : "+f"((d)[0]), "+f"((d)[1]), "+f"((d)[2]), "+f"((d)[3])      \
                 : "r"(a0), "r"(a1), "r"(a2), "r"(a3), "r"(b0), "r"(b1))

// ---------------- prepass: gso f32 -> fp16 k64-chunk images (144B rows) -----------
__global__ void prep_gso(const float* __restrict__ gso)
{
    int idx = blockIdx.x * blockDim.x + threadIdx.x;     // NCHUNK*336*64
    if (idx >= NCHUNK * 336 * 64) return;
    int kk = idx / (336 * 64);
    int r  = (idx / 64) % 336;
    int c  = idx & 63;
    int kg = kk * 64 + c;
    float val = (r < Vv && kg < Vv) ? gso[(size_t)r * Vv + kg] : 0.0f;
    *(__half*)(g_gso_f16 + (size_t)kk * GCH + r * GSTR + c * 2) = __float2half_rn(val);
}

// ---------------- main kernel: 12 warps, 32 M-rows per warp ----------------
__global__ void __launch_bounds__(TPB, 1)
gconv_hmma(const float* __restrict__ x, const float* __restrict__ gso,
           const float* __restrict__ w, const float* __restrict__ bias,
           float* __restrict__ out)
{
    extern __shared__ unsigned char smem[];
    const uint32_t sb = smem_u32(smem);
    const int tid = threadIdx.x, wid = tid >> 5, lid = tid & 31;
    const int bt = blockIdx.x, b = bt >> 6, t = bt & 63;

    // ---- kick off chunk-0 gso copy immediately (overlaps X staging + phase 1) ----
    copy_chunk(sb + SM_G, g_gso_f16, tid);
    asm volatile("cp.async.commit_group;" ::: "memory");

    // ---- bias -> smem ----
    if (tid < Cc) ((float*)(smem + SM_BIAS))[tid] = bias[tid];

    // ---- weights as B-operands [c][i] row-major (stride 72 fp16), single term ----
    // out = xp @ W[0] + (gso@xp) @ W[1] + bias + x
    for (int e = tid; e < Cc * Cc; e += TPB) {
        int i = e >> 6, c = e & 63;
        float w1 = w[Cc * Cc + e];                     // gso path (U = X@W1)
        float w0 = w[e] + (i == c ? 1.0f : 0.0f);      // direct path + residual fold
        uint32_t off = (uint32_t)(c * 144 + i * 2);
        *(__half*)(smem + SM_W + off)        = __float2half_rn(w1);
        *(__half*)(smem + SM_W + 9216 + off) = __float2half_rn(w0);
    }

    // ---- X as A-operand [v][i] row-major (stride 72 fp16), single term ----
    const float* xb = x + ((size_t)(b * Cc) * Tt + t) * Vv;
    #pragma unroll
    for (int ii = 0; ii < 6; ii++) {
        int i = wid + 12 * ii;
        if (i < Cc) {
            const float* xr = xb + (size_t)i * Tt * Vv;
            for (int v = lid; v < 384; v += 32) {
                float val = (v < Vv) ? xr[v] : 0.0f;
                uint32_t off = (uint32_t)((v >> 7) * XBLK + (v & 127) * 144 + i * 2);
                *(__half*)(smem + SM_X + off) = __float2half_rn(val);
            }
        }
    }
    __syncthreads();

    // ---- persistent out accumulators (2 m16 subtiles/warp), init with bias ----
    const float* bsm = (const float*)(smem + SM_BIAS);
    float oacc[2][8][4];
    #pragma unroll
    for (int s = 0; s < 2; s++)
        #pragma unroll
        for (int nt = 0; nt < 8; nt++)
            #pragma unroll
            for (int r = 0; r < 4; r++)
                oacc[s][nt][r] = bsm[nt * 8 + (lid & 3) * 2 + (r & 1)];

    // ================= phase 1: U = X@W1 ; oacc = bias + X@W0' (all single fp16) =====
    float uacc[2][8][4] = {};
    {
        const uint32_t xa0 = sb + SM_X + (wid >> 2) * XBLK +
                             ((wid & 3) * 32 + (lid & 15)) * 144 + (lid >> 4) * 16;
        #pragma unroll
        for (int k = 0; k < 4; k++) {
            uint32_t a[2][4];
            #pragma unroll
            for (int s = 0; s < 2; s++)
                LDSM4(a[s][0], a[s][1], a[s][2], a[s][3], xa0 + s * 2304 + k * 32);
            #pragma unroll
            for (int np = 0; np < 4; np++) {
                const uint32_t wa = sb + SM_W +
                    (np * 16 + (lid & 15)) * 144 + (lid >> 4) * 16 + k * 32;
                uint32_t h0, h1, h2, h3, g0, g1, g2, g3;
                LDSM4(h0, h1, h2, h3, wa);            // W1
                LDSM4(g0, g1, g2, g3, wa + 9216);     // W0'
                #pragma unroll
                for (int s = 0; s < 2; s++) {
                    MMA(uacc[s][np * 2],     a[s][0], a[s][1], a[s][2], a[s][3], h0, h2);
                    MMA(uacc[s][np * 2 + 1], a[s][0], a[s][1], a[s][2], a[s][3], h1, h3);
                    MMA(oacc[s][np * 2],     a[s][0], a[s][1], a[s][2], a[s][3], g0, g2);
                    MMA(oacc[s][np * 2 + 1], a[s][0], a[s][1], a[s][2], a[s][3], g1, g3);
                }
            }
        }
    }
    __syncthreads();   // all warps done reading X
    // write UT: [c][k'] single fp16, stride 272B per 128-block
    #pragma unroll
    for (int s = 0; s < 2; s++)
        #pragma unroll
        for (int nt = 0; nt < 8; nt++)
            #pragma unroll
            for (int r = 0; r < 4; r++) {
                int c  = nt * 8 + (lid & 3) * 2 + (r & 1);
                int kp = wid * 32 + s * 16 + (lid >> 2) + ((r >> 1) << 3);
                uint32_t off = (uint32_t)((kp >> 7) * XBLK + c * 272 + (kp & 127) * 2);
                *(__half*)(smem + SM_X + off) = __float2half_rn(uacc[s][nt][r]);
            }

    // wait for chunk-0 gso copy, make UT + G visible
    asm volatile("cp.async.wait_group 0;" ::: "memory");
    __syncthreads();

    // ================= phase 2: oacc += G @ U, k64 chunks, pipelined =================
    for (int kk = 0; kk < NCHUNK; kk++) {
        if (kk < NCHUNK - 1) {   // issue next chunk's copy before this chunk's MMAs
            copy_chunk(sb + SM_G + ((kk + 1) & 1) * GCH,
                       g_gso_f16 + (size_t)(kk + 1) * GCH, tid);
            asm volatile("cp.async.commit_group;" ::: "memory");
        }

        const uint32_t gb = sb + SM_G + (kk & 1) * GCH;
        const uint32_t ub = sb + SM_X + (kk >> 1) * XBLK + (kk & 1) * 128;

        #pragma unroll
        for (int ks = 0; ks < 4; ks++) {
            // U B-fragments for this k16 slice (shared across both m-subtiles)
            uint32_t uf[4][4];
            #pragma unroll
            for (int np = 0; np < 4; np++)
                LDSM4(uf[np][0], uf[np][1], uf[np][2], uf[np][3],
                      ub + (np * 16 + (lid & 15)) * 272 + (lid >> 4) * 16 + ks * 32);
            #pragma unroll
            for (int s = 0; s < 2; s++) {
                uint32_t a0, a1, a2, a3;
                LDSM4(a0, a1, a2, a3,
                      gb + (wid * 32 + s * 16 + (lid & 15)) * GSTR +
                      (lid >> 4) * 16 + ks * 32);
                #pragma unroll
                for (int np = 0; np < 4; np++) {
                    MMA(oacc[s][np * 2],     a0, a1, a2, a3, uf[np][0], uf[np][2]);
                    MMA(oacc[s][np * 2 + 1], a0, a1, a2, a3, uf[np][1], uf[np][3]);
                }
            }
        }

        if (kk < NCHUNK - 1) {
            asm volatile("cp.async.wait_group 0;" ::: "memory");
            __syncthreads();
        }
    }
    __syncthreads();

    // ================= epilogue: transpose via smem, coalesced [c][v] stores =========
    float* Os = (float*)(smem + SM_X);   // [64][396] f32, UT/W/G dead
    #pragma unroll
    for (int s = 0; s < 2; s++)
        #pragma unroll
        for (int nt = 0; nt < 8; nt++)
            #pragma unroll
            for (int r = 0; r < 4; r++) {
                int c = nt * 8 + (lid & 3) * 2 + (r & 1);
                int v = wid * 32 + s * 16 + (lid >> 2) + ((r >> 1) << 3);
                Os[c * 396 + v] = oacc[s][nt][r];
            }
    __syncthreads();
    float* ob = out + ((size_t)(b * Cc) * Tt + t) * Vv;
    for (int c = wid; c < Cc; c += 12) {
        float* orow = ob + (size_t)c * Tt * Vv;
        for (int v = lid; v < Vv; v += 32)
            orow[v] = Os[c * 396 + v];
    }
}

extern "C" void kernel_launch(void* const* d_in, const int* in_sizes, int n_in,
                              void* d_out, int out_size)
{
    const float* x      = (const float*)d_in[0];
    const float* gso    = (const float*)d_in[1];
    const float* weight = (const float*)d_in[2];
    const float* bias   = (const float*)d_in[3];
    float* out = (float*)d_out;

    prep_gso<<<(NCHUNK * 336 * 64 + 255) / 256, 256>>>(gso);

    cudaFuncSetAttribute(gconv_hmma,
                         cudaFuncAttributeMaxDynamicSharedMemorySize, SM_TOTAL);
    gconv_hmma<<<32 * 64, TPB, SM_TOTAL>>>(x, gso, weight, bias, out);
}

// round 16
// speedup vs baseline: 1.5140x; 1.2140x over previous
#include <cuda_runtime.h>
#include <cuda_fp16.h>
#include <cstdint>

namespace {
constexpr int Cc = 64, Tt = 64, Vv = 325, TPB = 768;
constexpr int NCHUNK = 11;       // k32 chunks (11*32 = 352 >= 325; k'>=325 hits zero U rows)
constexpr int XBLK  = 18432;     // X 128-v block: [128][72] fp16, 144B rows
constexpr int UBLK  = 17408;     // UT 128-k' block: [64][136] fp16, 272B rows
constexpr int GSTR  = 80;        // G row stride (16B-aligned, conflict-free)
constexpr int GCH   = 384 * GSTR;            // 30720 per chunk buffer
constexpr int SM_X  = 0;         // 3 x 18432 = 55296 ; (with UT) reused as Os in epilogue
constexpr int SM_UT = 55296;     // 3 x 17408 = 52224
constexpr int SM_W  = 107520;    // W1, W0' each [64][72] fp16 = 9216
constexpr int SM_G  = 125952;    // 2 bufs x 30720
constexpr int SM_BIAS = 187392;
constexpr int SM_TOTAL = 187648;
}

// Pre-converted gso, fp16: per chunk [336 rows x 32 k] at 80B row stride
__device__ __align__(16) unsigned char g_gso_f16[NCHUNK * GCH];   // ~338 KB

__device__ __forceinline__ uint32_t smem_u32(const void* p) {
    uint32_t a;
    asm("{ .reg .u64 tmp; cvta.to.shared.u64 tmp, %1; cvt.u32.u64 %0, tmp; }"
        : "=r"(a) : "l"(p));
    return a;
}
__device__ __forceinline__ void cpasync16(uint32_t dst, const void* src) {
    asm volatile("cp.async.cg.shared.global [%0], [%1], 16;"
                 :: "r"(dst), "l"(src) : "memory");
}
// copy one chunk: 1680 x 16B = 26880 B (rows 0-335; rows >=336 stale = discarded v)
__device__ __forceinline__ void copy_chunk(uint32_t dst, const unsigned char* src,
                                           int tid) {
    #pragma unroll
    for (int u = tid; u < 1680; u += TPB)
        cpasync16(dst + (uint32_t)u * 16, src + (uint32_t)u * 16);
}

#define LDSM4(r0, r1, r2, r3, addr)                                            \
    asm volatile("ldmatrix.sync.aligned.m8n8.x4.shared.b16 {%0,%1,%2,%3}, [%4];" \
                 : "=r"(r0), "=r"(r1), "=r"(r2), "=r"(r3) : "r"(addr))

#define MMA(d, a0, a1, a2, a3, b0, b1)                                         \
    asm volatile("mma.sync.aligned.m16n8k16.row.col.f32.f16.f16.f32 "          \
                 "{%0,%1,%2,%3},{%4,%5,%6,%7},{%8,%9},{%0,%1,%2,%3};"          \
                 : "+f"((d)[0]), "+f"((d)[1]), "+f"((d)[2]), "+f"((d)[3])      \
                 : "r"(a0), "r"(a1), "r"(a2), "r"(a3), "r"(b0), "r"(b1))

// ---------------- prepass: gso f32 -> fp16 k32-chunk images (80B rows) ------------
__global__ void prep_gso(const float* __restrict__ gso)
{
    int idx = blockIdx.x * blockDim.x + threadIdx.x;     // NCHUNK*336*32
    if (idx >= NCHUNK * 336 * 32) return;
    int kk = idx / (336 * 32);
    int r  = (idx / 32) % 336;
    int c  = idx & 31;
    int kg = kk * 32 + c;
    float val = (r < Vv && kg < Vv) ? gso[(size_t)r * Vv + kg] : 0.0f;
    *(__half*)(g_gso_f16 + (size_t)kk * GCH + r * GSTR + c * 2) = __float2half_rn(val);
}

// ------------- main: 24 warps, each owns 32 M-rows x 32 N-cols -------------
__global__ void __launch_bounds__(TPB, 1)
gconv_hmma(const float* __restrict__ x, const float* __restrict__ gso,
           const float* __restrict__ w, const float* __restrict__ bias,
           float* __restrict__ out)
{
    extern __shared__ unsigned char smem[];
    const uint32_t sb = smem_u32(smem);
    const int tid = threadIdx.x, wid = tid >> 5, lid = tid & 31;
    const int wp = wid >> 1;     // M-group: rows [wp*32, wp*32+32)
    const int nh = wid & 1;      // N-half: cols [nh*32, nh*32+32)
    const int bt = blockIdx.x, b = bt >> 6, t = bt & 63;

    // ---- kick off chunk-0 gso copy immediately (overlaps X staging + phase 1) ----
    copy_chunk(sb + SM_G, g_gso_f16, tid);
    asm volatile("cp.async.commit_group;" ::: "memory");

    // ---- bias -> smem ----
    if (tid < Cc) ((float*)(smem + SM_BIAS))[tid] = bias[tid];

    // ---- weights as B-operands [c][i] row-major (stride 144B), single fp16 ----
    // out = xp @ W[0] + (gso@xp) @ W[1] + bias + x
    for (int e = tid; e < Cc * Cc; e += TPB) {
        int i = e >> 6, c = e & 63;
        float w1 = w[Cc * Cc + e];                     // gso path (U = X@W1)
        float w0 = w[e] + (i == c ? 1.0f : 0.0f);      // direct path + residual fold
        uint32_t off = (uint32_t)(c * 144 + i * 2);
        *(__half*)(smem + SM_W + off)        = __float2half_rn(w1);
        *(__half*)(smem + SM_W + 9216 + off) = __float2half_rn(w0);
    }

    // ---- X as A-operand [v][i] row-major (stride 144B), single fp16 ----
    const float* xb = x + ((size_t)(b * Cc) * Tt + t) * Vv;
    #pragma unroll
    for (int ii = 0; ii < 3; ii++) {
        int i = wid + 24 * ii;
        if (i < Cc) {
            const float* xr = xb + (size_t)i * Tt * Vv;
            for (int v = lid; v < 384; v += 32) {
                float val = (v < Vv) ? xr[v] : 0.0f;
                uint32_t off = (uint32_t)((v >> 7) * XBLK + (v & 127) * 144 + i * 2);
                *(__half*)(smem + SM_X + off) = __float2half_rn(val);
            }
        }
    }
    __syncthreads();

    // warp's X A-fragment base for m16 subtile s (rows wp*32 + s*16 + ...)
    #define XA(s) (sb + SM_X + ((wp * 32 + (s) * 16) >> 7) * XBLK +             \
                   (((wp * 32 + (s) * 16) & 127) + (lid & 15)) * 144 +          \
                   (lid >> 4) * 16)
    // W fragment base for n16 subtile np (cols nh*32 + np*16 + ...)
    #define WA(np) (sb + SM_W + (nh * 32 + (np) * 16 + (lid & 15)) * 144 +      \
                    (lid >> 4) * 16)

    // ================= phase 1a: uacc = X@W1 (warp's 32x32 tile) =====================
    float uacc[2][4][4] = {};
    #pragma unroll
    for (int k = 0; k < 4; k++) {
        uint32_t a[2][4];
        #pragma unroll
        for (int s = 0; s < 2; s++)
            LDSM4(a[s][0], a[s][1], a[s][2], a[s][3], XA(s) + k * 32);
        #pragma unroll
        for (int np = 0; np < 2; np++) {
            uint32_t h0, h1, h2, h3;
            LDSM4(h0, h1, h2, h3, WA(np) + k * 32);
            #pragma unroll
            for (int s = 0; s < 2; s++) {
                MMA(uacc[s][np * 2],     a[s][0], a[s][1], a[s][2], a[s][3], h0, h2);
                MMA(uacc[s][np * 2 + 1], a[s][0], a[s][1], a[s][2], a[s][3], h1, h3);
            }
        }
    }
    // write UT (own region, no X overlap): [c][k'] single fp16, 272B rows per UBLK
    #pragma unroll
    for (int s = 0; s < 2; s++)
        #pragma unroll
        for (int nt = 0; nt < 4; nt++)
            #pragma unroll
            for (int r = 0; r < 4; r++) {
                int c  = nh * 32 + nt * 8 + (lid & 3) * 2 + (r & 1);
                int kp = wp * 32 + s * 16 + (lid >> 2) + ((r >> 1) << 3);
                uint32_t off = (uint32_t)((kp >> 7) * UBLK + c * 272 + (kp & 127) * 2);
                *(__half*)(smem + SM_UT + off) = __float2half_rn(uacc[s][nt][r]);
            }

    // ================= phase 1b: oacc = bias + X@W0' (uacc now dead) =================
    const float* bsm = (const float*)(smem + SM_BIAS);
    float oacc[2][4][4];
    #pragma unroll
    for (int s = 0; s < 2; s++)
        #pragma unroll
        for (int nt = 0; nt < 4; nt++)
            #pragma unroll
            for (int r = 0; r < 4; r++)
                oacc[s][nt][r] = bsm[nh * 32 + nt * 8 + (lid & 3) * 2 + (r & 1)];
    #pragma unroll
    for (int k = 0; k < 4; k++) {
        uint32_t a[2][4];
        #pragma unroll
        for (int s = 0; s < 2; s++)
            LDSM4(a[s][0], a[s][1], a[s][2], a[s][3], XA(s) + k * 32);
        #pragma unroll
        for (int np = 0; np < 2; np++) {
            uint32_t g0, g1, g2, g3;
            LDSM4(g0, g1, g2, g3, WA(np) + 9216 + k * 32);
            #pragma unroll
            for (int s = 0; s < 2; s++) {
                MMA(oacc[s][np * 2],     a[s][0], a[s][1], a[s][2], a[s][3], g0, g2);
                MMA(oacc[s][np * 2 + 1], a[s][0], a[s][1], a[s][2], a[s][3], g1, g3);
            }
        }
    }

    // wait for chunk-0 gso copy; make UT visible to all warps
    asm volatile("cp.async.wait_group 0;" ::: "memory");
    __syncthreads();

    // ================= phase 2: oacc += G @ U, k32 chunks, pipelined =================
    for (int kk = 0; kk < NCHUNK; kk++) {
        if (kk < NCHUNK - 1) {
            copy_chunk(sb + SM_G + ((kk + 1) & 1) * GCH,
                       g_gso_f16 + (size_t)(kk + 1) * GCH, tid);
            asm volatile("cp.async.commit_group;" ::: "memory");
        }

        const uint32_t gb = sb + SM_G + (kk & 1) * GCH;
        const uint32_t ub = sb + SM_UT + (kk >> 2) * UBLK + (kk & 3) * 64;

        #pragma unroll
        for (int ks = 0; ks < 2; ks++) {
            uint32_t uf[2][4];
            #pragma unroll
            for (int np = 0; np < 2; np++)
                LDSM4(uf[np][0], uf[np][1], uf[np][2], uf[np][3],
                      ub + (nh * 32 + np * 16 + (lid & 15)) * 272 +
                      (lid >> 4) * 16 + ks * 32);
            #pragma unroll
            for (int s = 0; s < 2; s++) {
                uint32_t a0, a1, a2, a3;
                LDSM4(a0, a1, a2, a3,
                      gb + (wp * 32 + s * 16 + (lid & 15)) * GSTR +
                      (lid >> 4) * 16 + ks * 32);
                #pragma unroll
                for (int np = 0; np < 2; np++) {
                    MMA(oacc[s][np * 2],     a0, a1, a2, a3, uf[np][0], uf[np][2]);
                    MMA(oacc[s][np * 2 + 1], a0, a1, a2, a3, uf[np][1], uf[np][3]);
                }
            }
        }

        if (kk < NCHUNK - 1) {
            asm volatile("cp.async.wait_group 0;" ::: "memory");
            __syncthreads();
        }
    }
    __syncthreads();

    // ================= epilogue: transpose via smem, coalesced [c][v] stores =========
    float* Os = (float*)(smem + SM_X);   // [64][396] f32 = 101376 B over X+UT (dead)
    #pragma unroll
    for (int s = 0; s < 2; s++)
        #pragma unroll
        for (int nt = 0; nt < 4; nt++)
            #pragma unroll
            for (int r = 0; r < 4; r++) {
                int c = nh * 32 + nt * 8 + (lid & 3) * 2 + (r & 1);
                int v = wp * 32 + s * 16 + (lid >> 2) + ((r >> 1) << 3);
                Os[c * 396 + v] = oacc[s][nt][r];
            }
    __syncthreads();
    float* ob = out + ((size_t)(b * Cc) * Tt + t) * Vv;
    for (int c = wid; c < Cc; c += 24) {
        float* orow = ob + (size_t)c * Tt * Vv;
        for (int v = lid; v < Vv; v += 32)
            orow[v] = Os[c * 396 + v];
    }
}

extern "C" void kernel_launch(void* const* d_in, const int* in_sizes, int n_in,
                              void* d_out, int out_size)
{
    const float* x      = (const float*)d_in[0];
    const float* gso    = (const float*)d_in[1];
    const float* weight = (const float*)d_in[2];
    const float* bias   = (const float*)d_in[3];
    float* out = (float*)d_out;

    prep_gso<<<(NCHUNK * 336 * 32 + 255) / 256, 256>>>(gso);

    cudaFuncSetAttribute(gconv_hmma,
                         cudaFuncAttributeMaxDynamicSharedMemorySize, SM_TOTAL);
    gconv_hmma<<<32 * 64, TPB, SM_TOTAL>>>(x, gso, weight, bias, out);
}

// round 17
// speedup vs baseline: 1.7614x; 1.1634x over previous
#include <cuda_runtime.h>
#include <cuda_fp16.h>
#include <cstdint>

namespace {
constexpr int Cc = 64, Tt = 64, Vv = 325, TPB = 768;
constexpr int NCHUNK = 21;       // k16 chunks (21*16 = 336 >= 325)
constexpr int XBLK  = 18432;     // X 128-v block: [128][72] fp16, 144B rows
constexpr int UBLK  = 17408;     // UT 128-k' block: [64][136] fp16, 272B rows
constexpr int GSTR  = 48;        // G row stride (16B-aligned; 12-word: conflict-free)
constexpr int GCHG  = 384 * GSTR;            // global chunk stride = 18432
constexpr int GSLAB = 32 * GSTR;             // per-warp slab = 1536 B
constexpr int SM_X  = 0;         // 3 x 18432 = 55296 ; (with UT) reused as Os
constexpr int SM_UT = 55296;     // 3 x 17408 = 52224
constexpr int SM_W  = 107520;    // W1, W0' each [64][72] fp16 = 9216
constexpr int SM_G  = 125952;    // 24 warps x 2 slabs x 1536 = 73728
constexpr int SM_BIAS = 199680;
constexpr int SM_TOTAL = 199936;
}

// Pre-converted gso, fp16: per chunk [384 rows x 16 k] at 48B stride (rows>=336 zero)
__device__ __align__(16) unsigned char g_gso_f16[NCHUNK * GCHG];   // ~387 KB

__device__ __forceinline__ uint32_t smem_u32(const void* p) {
    uint32_t a;
    asm("{ .reg .u64 tmp; cvta.to.shared.u64 tmp, %1; cvt.u32.u64 %0, tmp; }"
        : "=r"(a) : "l"(p));
    return a;
}
__device__ __forceinline__ void cpasync16(uint32_t dst, const void* src) {
    asm volatile("cp.async.cg.shared.global [%0], [%1], 16;"
                 :: "r"(dst), "l"(src) : "memory");
}
// warp-private slab copy: 96 x 16B over 32 lanes = 3 per lane
__device__ __forceinline__ void copy_slab(uint32_t dst, const unsigned char* src,
                                          int lid) {
    #pragma unroll
    for (int j = 0; j < 3; j++)
        cpasync16(dst + (uint32_t)(lid + j * 32) * 16, src + (lid + j * 32) * 16);
}

#define LDSM4(r0, r1, r2, r3, addr)                                            \
    asm volatile("ldmatrix.sync.aligned.m8n8.x4.shared.b16 {%0,%1,%2,%3}, [%4];" \
                 : "=r"(r0), "=r"(r1), "=r"(r2), "=r"(r3) : "r"(addr))

#define MMA(d, a0, a1, a2, a3, b0, b1)                                         \
    asm volatile("mma.sync.aligned.m16n8k16.row.col.f32.f16.f16.f32 "          \
                 "{%0,%1,%2,%3},{%4,%5,%6,%7},{%8,%9},{%0,%1,%2,%3};"          \
                 : "+f"((d)[0]), "+f"((d)[1]), "+f"((d)[2]), "+f"((d)[3])      \
                 : "r"(a0), "r"(a1), "r"(a2), "r"(a3), "r"(b0), "r"(b1))

// ---------------- prepass: gso f32 -> fp16 k16-chunk images (48B rows, 384 rows) ---
__global__ void prep_gso(const float* __restrict__ gso)
{
    int idx = blockIdx.x * blockDim.x + threadIdx.x;     // NCHUNK*384*16
    if (idx >= NCHUNK * 384 * 16) return;
    int kk = idx / (384 * 16);
    int r  = (idx / 16) % 384;
    int c  = idx & 15;
    int kg = kk * 16 + c;
    float val = (r < Vv && kg < Vv) ? gso[(size_t)r * Vv + kg] : 0.0f;
    *(__half*)(g_gso_f16 + (size_t)kk * GCHG + r * GSTR + c * 2) = __float2half_rn(val);
}

// ------------- main: 24 warps, each owns 32 M-rows x 32 N-cols -------------
__global__ void __launch_bounds__(TPB, 1)
gconv_hmma(const float* __restrict__ x, const float* __restrict__ gso,
           const float* __restrict__ w, const float* __restrict__ bias,
           float* __restrict__ out)
{
    extern __shared__ unsigned char smem[];
    const uint32_t sb = smem_u32(smem);
    const int tid = threadIdx.x, wid = tid >> 5, lid = tid & 31;
    const int wp = wid >> 1;     // M-group: rows [wp*32, wp*32+32)
    const int nh = wid & 1;      // N-half: cols [nh*32, nh*32+32)
    const int bt = blockIdx.x, b = bt >> 6, t = bt & 63;

    // ---- per-warp G pipeline: prefetch chunks 0,1 into this warp's two slabs ----
    const unsigned char* gwarp = g_gso_f16 + wp * GSLAB;
    const uint32_t gslab = sb + SM_G + (uint32_t)wid * (2 * GSLAB);
    copy_slab(gslab, gwarp, lid);
    asm volatile("cp.async.commit_group;" ::: "memory");
    copy_slab(gslab + GSLAB, gwarp + GCHG, lid);
    asm volatile("cp.async.commit_group;" ::: "memory");

    // ---- bias -> smem ----
    if (tid < Cc) ((float*)(smem + SM_BIAS))[tid] = bias[tid];

    // ---- weights as B-operands [c][i] (stride 144B), fp16, half2-vectorized ----
    // out = xp @ W[0] + (gso@xp) @ W[1] + bias + x
    for (int e = tid; e < 32 * Cc; e += TPB) {
        int ip = e >> 6, c = e & 63, i = ip * 2;
        float w1a = w[Cc * Cc + i * Cc + c], w1b = w[Cc * Cc + (i + 1) * Cc + c];
        float w0a = w[i * Cc + c] + (i == c ? 1.0f : 0.0f);
        float w0b = w[(i + 1) * Cc + c] + ((i + 1) == c ? 1.0f : 0.0f);
        uint32_t off = (uint32_t)(c * 144 + i * 2);
        *(__half2*)(smem + SM_W + off)        = __floats2half2_rn(w1a, w1b);
        *(__half2*)(smem + SM_W + 9216 + off) = __floats2half2_rn(w0a, w0b);
    }

    // ---- X as A-operand [v][i] (stride 144B), fp16, half2 over channel pairs ----
    const float* xb = x + ((size_t)(b * Cc) * Tt + t) * Vv;
    #pragma unroll
    for (int ii = 0; ii < 2; ii++) {
        int p = wid + 24 * ii;           // channel-pair index 0..31
        if (p < 32) {
            const float* x0 = xb + (size_t)(2 * p) * Tt * Vv;
            const float* x1 = x0 + (size_t)Tt * Vv;
            for (int v = lid; v < 384; v += 32) {
                float f0 = (v < Vv) ? x0[v] : 0.0f;
                float f1 = (v < Vv) ? x1[v] : 0.0f;
                uint32_t off = (uint32_t)((v >> 7) * XBLK + (v & 127) * 144 + 4 * p);
                *(__half2*)(smem + SM_X + off) = __floats2half2_rn(f0, f1);
            }
        }
    }
    __syncthreads();

    #define XA(s) (sb + SM_X + ((wp * 32 + (s) * 16) >> 7) * XBLK +             \
                   (((wp * 32 + (s) * 16) & 127) + (lid & 15)) * 144 +          \
                   (lid >> 4) * 16)
    #define WA(np) (sb + SM_W + (nh * 32 + (np) * 16 + (lid & 15)) * 144 +      \
                    (lid >> 4) * 16)

    // ================= phase 1a: uacc = X@W1 (warp's 32x32 tile) =====================
    float uacc[2][4][4] = {};
    #pragma unroll
    for (int k = 0; k < 4; k++) {
        uint32_t a[2][4];
        #pragma unroll
        for (int s = 0; s < 2; s++)
            LDSM4(a[s][0], a[s][1], a[s][2], a[s][3], XA(s) + k * 32);
        #pragma unroll
        for (int np = 0; np < 2; np++) {
            uint32_t h0, h1, h2, h3;
            LDSM4(h0, h1, h2, h3, WA(np) + k * 32);
            #pragma unroll
            for (int s = 0; s < 2; s++) {
                MMA(uacc[s][np * 2],     a[s][0], a[s][1], a[s][2], a[s][3], h0, h2);
                MMA(uacc[s][np * 2 + 1], a[s][0], a[s][1], a[s][2], a[s][3], h1, h3);
            }
        }
    }
    // write UT (own region): [c][k'] single fp16, 272B rows per UBLK
    #pragma unroll
    for (int s = 0; s < 2; s++)
        #pragma unroll
        for (int nt = 0; nt < 4; nt++)
            #pragma unroll
            for (int r = 0; r < 4; r++) {
                int c  = nh * 32 + nt * 8 + (lid & 3) * 2 + (r & 1);
                int kp = wp * 32 + s * 16 + (lid >> 2) + ((r >> 1) << 3);
                uint32_t off = (uint32_t)((kp >> 7) * UBLK + c * 272 + (kp & 127) * 2);
                *(__half*)(smem + SM_UT + off) = __float2half_rn(uacc[s][nt][r]);
            }

    // ================= phase 1b: oacc = bias + X@W0' (uacc dead) =====================
    const float* bsm = (const float*)(smem + SM_BIAS);
    float oacc[2][4][4];
    #pragma unroll
    for (int s = 0; s < 2; s++)
        #pragma unroll
        for (int nt = 0; nt < 4; nt++)
            #pragma unroll
            for (int r = 0; r < 4; r++)
                oacc[s][nt][r] = bsm[nh * 32 + nt * 8 + (lid & 3) * 2 + (r & 1)];
    #pragma unroll
    for (int k = 0; k < 4; k++) {
        uint32_t a[2][4];
        #pragma unroll
        for (int s = 0; s < 2; s++)
            LDSM4(a[s][0], a[s][1], a[s][2], a[s][3], XA(s) + k * 32);
        #pragma unroll
        for (int np = 0; np < 2; np++) {
            uint32_t g0, g1, g2, g3;
            LDSM4(g0, g1, g2, g3, WA(np) + 9216 + k * 32);
            #pragma unroll
            for (int s = 0; s < 2; s++) {
                MMA(oacc[s][np * 2],     a[s][0], a[s][1], a[s][2], a[s][3], g0, g2);
                MMA(oacc[s][np * 2 + 1], a[s][0], a[s][1], a[s][2], a[s][3], g1, g3);
            }
        }
    }
    __syncthreads();   // UT visible to all warps; X reads done

    // ============ phase 2: oacc += G @ U — warp-private slabs, NO block syncs ========
    for (int kk = 0; kk < NCHUNK; kk++) {
        if (kk < NCHUNK - 1)
            asm volatile("cp.async.wait_group 1;" ::: "memory");
        else
            asm volatile("cp.async.wait_group 0;" ::: "memory");
        __syncwarp();

        const uint32_t gb = gslab + (uint32_t)(kk & 1) * GSLAB;
        const uint32_t ub = sb + SM_UT + (kk >> 3) * UBLK + (kk & 7) * 32;

        uint32_t uf[2][4];
        #pragma unroll
        for (int np = 0; np < 2; np++)
            LDSM4(uf[np][0], uf[np][1], uf[np][2], uf[np][3],
                  ub + (nh * 32 + np * 16 + (lid & 15)) * 272 + (lid >> 4) * 16);
        #pragma unroll
        for (int s = 0; s < 2; s++) {
            uint32_t a0, a1, a2, a3;
            LDSM4(a0, a1, a2, a3,
                  gb + (s * 16 + (lid & 15)) * GSTR + (lid >> 4) * 16);
            #pragma unroll
            for (int np = 0; np < 2; np++) {
                MMA(oacc[s][np * 2],     a0, a1, a2, a3, uf[np][0], uf[np][2]);
                MMA(oacc[s][np * 2 + 1], a0, a1, a2, a3, uf[np][1], uf[np][3]);
            }
        }

        if (kk < NCHUNK - 2) {   // refill the slab just consumed (reads already issued)
            copy_slab(gb, gwarp + (size_t)(kk + 2) * GCHG, lid);
            asm volatile("cp.async.commit_group;" ::: "memory");
        }
    }
    __syncthreads();   // all warps done with UT/X before Os overlays them

    // ================= epilogue: transpose via smem, coalesced [c][v] stores =========
    float* Os = (float*)(smem + SM_X);   // [64][396] f32 over X+UT (dead)
    #pragma unroll
    for (int s = 0; s < 2; s++)
        #pragma unroll
        for (int nt = 0; nt < 4; nt++)
            #pragma unroll
            for (int r = 0; r < 4; r++) {
                int c = nh * 32 + nt * 8 + (lid & 3) * 2 + (r & 1);
                int v = wp * 32 + s * 16 + (lid >> 2) + ((r >> 1) << 3);
                Os[c * 396 + v] = oacc[s][nt][r];
            }
    __syncthreads();
    float* ob = out + ((size_t)(b * Cc) * Tt + t) * Vv;
    for (int c = wid; c < Cc; c += 24) {
        float* orow = ob + (size_t)c * Tt * Vv;
        for (int v = lid; v < Vv; v += 32)
            orow[v] = Os[c * 396 + v];
    }
}

extern "C" void kernel_launch(void* const* d_in, const int* in_sizes, int n_in,
                              void* d_out, int out_size)
{
    const float* x      = (const float*)d_in[0];
    const float* gso    = (const float*)d_in[1];
    const float* weight = (const float*)d_in[2];
    const float* bias   = (const float*)d_in[3];
    float* out = (float*)d_out;

    prep_gso<<<(NCHUNK * 384 * 16 + 255) / 256, 256>>>(gso);

    cudaFuncSetAttribute(gconv_hmma,
                         cudaFuncAttributeMaxDynamicSharedMemorySize, SM_TOTAL);
    gconv_hmma<<<32 * 64, TPB, SM_TOTAL>>>(x, gso, weight, bias, out);
}